// round 3
// baseline (speedup 1.0000x reference)
#include <cuda_runtime.h>
#include <math.h>

#define KC       10
#define BT       256
#define NC       1152
#define ICC      8
#define OC       16
#define BTILE    2
#define NTHREADS 512
#define NWARP    (NTHREADS / 32)

struct SmemLayout {
    float uh[BTILE][NC][OC];        // 147456 B  u_hat, fp32
    float logit[BTILE][NC];         // 9216 B    b_ij (scalar per n; broadcast over o)
    float cbuf[BTILE][NC];          // 9216 B    exp(logit - m)
    float red[NWARP][BTILE][OC];    // 2048 B    per-warp reduction partials
    float m_sm[BTILE];
    float z_sm[BTILE];
    float v_sm[BTILE][OC];
};

// s = sum_n c[n] * uh[n][:], then squash -> v_sm. Optionally write final output.
__device__ __forceinline__ void pass_s_and_squash(SmemLayout* sm, int t, bool useC,
                                                  bool writeOut, float* out, int k, int b0) {
    const int o    = t & 15;
    const int r2   = t >> 4;     // 0..31
    const int lane = t & 31;
    const int w    = t >> 5;
    float acc0 = 0.f, acc1 = 0.f;
    for (int n = r2; n < NC; n += 32) {        // conflict-free: half-warps read consecutive rows
        const float c0 = useC ? sm->cbuf[0][n] : 1.0f;
        const float c1 = useC ? sm->cbuf[1][n] : 1.0f;
        acc0 = fmaf(c0, sm->uh[0][n][o], acc0);
        acc1 = fmaf(c1, sm->uh[1][n][o], acc1);
    }
    acc0 += __shfl_xor_sync(0xffffffffu, acc0, 16);
    acc1 += __shfl_xor_sync(0xffffffffu, acc1, 16);
    if (lane < 16) { sm->red[w][0][o] = acc0; sm->red[w][1][o] = acc1; }
    __syncthreads();
    if (t < 32) {
        const int b = t >> 4;
        float s = 0.f;
        #pragma unroll
        for (int w2 = 0; w2 < NWARP; w2++) s += sm->red[w2][b][o];
        const float scale = useC ? (1.0f / sm->z_sm[b]) : (1.0f / (float)NC);
        s *= scale;
        float sq = s * s;
        #pragma unroll
        for (int sft = 1; sft < 16; sft <<= 1)
            sq += __shfl_xor_sync(0xffffffffu, sq, sft);
        // squash: v = s * ||s|| / (1 + ||s||^2)
        const float v = s * sqrtf(sq) / (1.0f + sq);
        sm->v_sm[b][o] = v;
        if (writeOut)
            out[((size_t)k * BT + b0 + b) * OC + o] = v;
    }
    __syncthreads();
}

// logit[n] (+)= dot(uh[n][:], v[:])
__device__ __forceinline__ void pass_a(SmemLayout* sm, int t, bool addMode) {
    const int o  = t & 15;
    const int r2 = t >> 4;
    const float v0 = sm->v_sm[0][o];
    const float v1 = sm->v_sm[1][o];
    for (int n = r2; n < NC; n += 32) {
        float p0 = sm->uh[0][n][o] * v0;
        float p1 = sm->uh[1][n][o] * v1;
        #pragma unroll
        for (int sft = 1; sft < 16; sft <<= 1) {
            p0 += __shfl_xor_sync(0xffffffffu, p0, sft);
            p1 += __shfl_xor_sync(0xffffffffu, p1, sft);
        }
        if (o == 0) {
            if (addMode) { sm->logit[0][n] += p0; sm->logit[1][n] += p1; }
            else         { sm->logit[0][n]  = p0; sm->logit[1][n]  = p1; }
        }
    }
    __syncthreads();
}

// softmax prep over n: m = max logit, cbuf = exp(logit - m), Z = sum cbuf
__device__ __forceinline__ void pass_mz(SmemLayout* sm, int t) {
    const int lane = t & 31, w = t >> 5;
    float m0 = -1e30f, m1 = -1e30f;
    for (int n = t; n < NC; n += NTHREADS) {
        m0 = fmaxf(m0, sm->logit[0][n]);
        m1 = fmaxf(m1, sm->logit[1][n]);
    }
    #pragma unroll
    for (int sft = 16; sft >= 1; sft >>= 1) {
        m0 = fmaxf(m0, __shfl_xor_sync(0xffffffffu, m0, sft));
        m1 = fmaxf(m1, __shfl_xor_sync(0xffffffffu, m1, sft));
    }
    if (lane == 0) { sm->red[w][0][0] = m0; sm->red[w][1][0] = m1; }
    __syncthreads();
    if (t < BTILE) {
        float m = -1e30f;
        #pragma unroll
        for (int w2 = 0; w2 < NWARP; w2++) m = fmaxf(m, sm->red[w2][t][0]);
        sm->m_sm[t] = m;
    }
    __syncthreads();
    float z0 = 0.f, z1 = 0.f;
    const float mm0 = sm->m_sm[0], mm1 = sm->m_sm[1];
    for (int n = t; n < NC; n += NTHREADS) {
        const float e0 = __expf(sm->logit[0][n] - mm0);
        const float e1 = __expf(sm->logit[1][n] - mm1);
        sm->cbuf[0][n] = e0; sm->cbuf[1][n] = e1;
        z0 += e0; z1 += e1;
    }
    #pragma unroll
    for (int sft = 16; sft >= 1; sft >>= 1) {
        z0 += __shfl_xor_sync(0xffffffffu, z0, sft);
        z1 += __shfl_xor_sync(0xffffffffu, z1, sft);
    }
    if (lane == 0) { sm->red[w][0][1] = z0; sm->red[w][1][1] = z1; }
    __syncthreads();
    if (t < BTILE) {
        float z = 0.f;
        #pragma unroll
        for (int w2 = 0; w2 < NWARP; w2++) z += sm->red[w2][t][1];
        sm->z_sm[t] = z;
    }
    __syncthreads();
}

__global__ __launch_bounds__(NTHREADS, 1)
void caps_routing_kernel(const float* __restrict__ u, const float* __restrict__ W,
                         float* __restrict__ out) {
    extern __shared__ char smem_bytes[];
    SmemLayout* sm = reinterpret_cast<SmemLayout*>(smem_bytes);

    const int k  = blockIdx.y;
    const int b0 = blockIdx.x * BTILE;
    const int t  = threadIdx.x;

    // ---- Phase 1: u_hat[b][n][o] = sum_i u[b][n][i] * W[k][n][i][o] into SMEM ----
    {
        const int oq = t & 3;        // which float4 of the 16-wide output row
        const int r  = t >> 2;       // 0..127
        const float* Wk  = W + (size_t)k * NC * ICC * OC;
        const float* ub0 = u + (size_t)b0 * NC * ICC;
        const float* ub1 = ub0 + (size_t)NC * ICC;
        for (int n = r; n < NC; n += 128) {
            const float4 a0 = *(const float4*)(ub0 + (size_t)n * ICC);
            const float4 a1 = *(const float4*)(ub0 + (size_t)n * ICC + 4);
            const float4 c0 = *(const float4*)(ub1 + (size_t)n * ICC);
            const float4 c1 = *(const float4*)(ub1 + (size_t)n * ICC + 4);
            const float u0[8] = {a0.x, a0.y, a0.z, a0.w, a1.x, a1.y, a1.z, a1.w};
            const float u1[8] = {c0.x, c0.y, c0.z, c0.w, c1.x, c1.y, c1.z, c1.w};
            float4 acc0 = make_float4(0.f, 0.f, 0.f, 0.f);
            float4 acc1 = make_float4(0.f, 0.f, 0.f, 0.f);
            const float* wp = Wk + (size_t)n * ICC * OC + oq * 4;
            #pragma unroll
            for (int i = 0; i < ICC; i++) {
                const float4 wv = *(const float4*)(wp + i * OC);
                acc0.x = fmaf(wv.x, u0[i], acc0.x);
                acc0.y = fmaf(wv.y, u0[i], acc0.y);
                acc0.z = fmaf(wv.z, u0[i], acc0.z);
                acc0.w = fmaf(wv.w, u0[i], acc0.w);
                acc1.x = fmaf(wv.x, u1[i], acc1.x);
                acc1.y = fmaf(wv.y, u1[i], acc1.y);
                acc1.z = fmaf(wv.z, u1[i], acc1.z);
                acc1.w = fmaf(wv.w, u1[i], acc1.w);
            }
            *(float4*)&sm->uh[0][n][oq * 4] = acc0;   // lanes write contiguous 512B: conflict-free
            *(float4*)&sm->uh[1][n][oq * 4] = acc1;
        }
    }
    __syncthreads();

    // ---- Routing iteration 0: b_ij = 0 => softmax is exactly uniform (1/N) ----
    pass_s_and_squash(sm, t, /*useC=*/false, /*writeOut=*/false, out, k, b0);
    pass_a(sm, t, /*addMode=*/false);          // logit = a0

    // ---- Iteration 1 ----
    pass_mz(sm, t);
    pass_s_and_squash(sm, t, /*useC=*/true, /*writeOut=*/false, out, k, b0);
    pass_a(sm, t, /*addMode=*/true);           // logit = a0 + a1

    // ---- Iteration 2 (final): softmax, s, squash -> output ----
    pass_mz(sm, t);
    pass_s_and_squash(sm, t, /*useC=*/true, /*writeOut=*/true, out, k, b0);
}

extern "C" void kernel_launch(void* const* d_in, const int* in_sizes, int n_in,
                              void* d_out, int out_size) {
    const float* u = (const float*)d_in[0];   // [256, 1152, 8]
    const float* W = (const float*)d_in[1];   // [10, 1152, 8, 16]
    float* out = (float*)d_out;               // [10, 256, 1, 1, 16]

    cudaFuncSetAttribute(caps_routing_kernel,
                         cudaFuncAttributeMaxDynamicSharedMemorySize,
                         (int)sizeof(SmemLayout));
    dim3 grid(BT / BTILE, KC);                // 128 x 10 = 1280 CTAs
    caps_routing_kernel<<<grid, NTHREADS, sizeof(SmemLayout)>>>(u, W, out);
}

// round 4
// speedup vs baseline: 1.4793x; 1.4793x over previous
#include <cuda_runtime.h>
#include <math.h>

#define KC       10
#define BT       256
#define NC       1152
#define ICC      8
#define OC       16
#define BTILE    2
#define NTHREADS 512
#define NWARP    (NTHREADS / 32)
#define PAD      20            // uh row stride in floats: 20 mod 32 -> conflict-free f4 row reads

struct SmemLayout {
    float  uh[BTILE][NC][PAD];        // 184320 B  u_hat fp32, padded rows
    float  logit[BTILE][NC];          // 9216 B
    float  cbuf[BTILE][NC];           // 9216 B    exp(logit)   (unnormalized)
    float4 sredA[NWARP][4][BTILE];    // 2048 B    phase-1 fused s0 partials (per oq)
    float4 sredB[NWARP][BTILE];       // 512 B     weighted pass_s partials (per warp-o4)
    float  zred[NWARP][BTILE];        // 128 B     per-warp Z partials
    float4 v4[BTILE][4];              // 128 B     v_j
};

// Final 32-thread stage: combine warp partials, divide by Z, squash -> v (and maybe out).
// mode 0: partials in sredA (16 warps x 4 oq), Z = NC (uniform c)
// mode 1: partials in sredB (warp w owns o4 = w>>2), Z = sum(zred)
__device__ __forceinline__ void squash_stage(SmemLayout* sm, int t, int mode,
                                             bool writeOut, float* out, int k, int b0) {
    if (t < 32) {
        const int b = t >> 4, o = t & 15, og = o >> 2, oc = o & 3;
        float s = 0.f, Z;
        if (mode == 0) {
            #pragma unroll
            for (int w = 0; w < NWARP; w++)
                s += ((const float*)&sm->sredA[w][og][b])[oc];
            Z = (float)NC;
        } else {
            #pragma unroll
            for (int j = 0; j < 4; j++)
                s += ((const float*)&sm->sredB[og * 4 + j][b])[oc];
            Z = 0.f;
            #pragma unroll
            for (int w = 0; w < NWARP; w++) Z += sm->zred[w][b];
        }
        s /= Z;
        float sq = s * s;
        #pragma unroll
        for (int sft = 1; sft < 16; sft <<= 1)
            sq += __shfl_xor_sync(0xffffffffu, sq, sft);
        const float v = s * sqrtf(sq) / (1.0f + sq);     // squash
        ((float*)&sm->v4[b])[o] = v;
        if (writeOut)
            out[((size_t)k * BT + b0 + b) * OC + o] = v;
    }
    __syncthreads();
}

// Weighted s: s[o] = sum_n cbuf[n] * uh[n][o].  Warp w owns o4 = w>>2; lanes stride rows.
__device__ __forceinline__ void pass_s_weighted(SmemLayout* sm, int t) {
    const int o4 = t >> 7;            // 0..3
    const int r  = t & 127;
    const int lane = t & 31, w = t >> 5;
    float4 a0 = make_float4(0.f,0.f,0.f,0.f), a1 = make_float4(0.f,0.f,0.f,0.f);
    #pragma unroll
    for (int it = 0; it < NC / 128; it++) {
        const int n = r + it * 128;
        const float c0 = sm->cbuf[0][n];
        const float c1 = sm->cbuf[1][n];
        const float4 h0 = *(const float4*)&sm->uh[0][n][o4 * 4];
        const float4 h1 = *(const float4*)&sm->uh[1][n][o4 * 4];
        a0.x = fmaf(c0, h0.x, a0.x); a0.y = fmaf(c0, h0.y, a0.y);
        a0.z = fmaf(c0, h0.z, a0.z); a0.w = fmaf(c0, h0.w, a0.w);
        a1.x = fmaf(c1, h1.x, a1.x); a1.y = fmaf(c1, h1.y, a1.y);
        a1.z = fmaf(c1, h1.z, a1.z); a1.w = fmaf(c1, h1.w, a1.w);
    }
    #pragma unroll
    for (int sft = 16; sft >= 1; sft >>= 1) {
        a0.x += __shfl_xor_sync(0xffffffffu, a0.x, sft);
        a0.y += __shfl_xor_sync(0xffffffffu, a0.y, sft);
        a0.z += __shfl_xor_sync(0xffffffffu, a0.z, sft);
        a0.w += __shfl_xor_sync(0xffffffffu, a0.w, sft);
        a1.x += __shfl_xor_sync(0xffffffffu, a1.x, sft);
        a1.y += __shfl_xor_sync(0xffffffffu, a1.y, sft);
        a1.z += __shfl_xor_sync(0xffffffffu, a1.z, sft);
        a1.w += __shfl_xor_sync(0xffffffffu, a1.w, sft);
    }
    if (lane == 0) { sm->sredB[w][0] = a0; sm->sredB[w][1] = a1; }
    __syncthreads();
}

// logit update + exp + Z, fused, shuffle-free row dot products.
__device__ __forceinline__ void pass_a_exp(SmemLayout* sm, int t, bool addMode) {
    const int lane = t & 31, w = t >> 5;
    float z0 = 0.f, z1 = 0.f;
    for (int idx = t; idx < BTILE * NC; idx += NTHREADS) {
        const int b = (idx >= NC) ? 1 : 0;
        const int n = idx - b * NC;
        const float4* hr = (const float4*)&sm->uh[b][n][0];
        const float4 h0 = hr[0], h1 = hr[1], h2 = hr[2], h3 = hr[3];
        const float4 v0 = sm->v4[b][0], v1 = sm->v4[b][1];
        const float4 v2 = sm->v4[b][2], v3 = sm->v4[b][3];
        float p = h0.x * v0.x;
        p = fmaf(h0.y, v0.y, p); p = fmaf(h0.z, v0.z, p); p = fmaf(h0.w, v0.w, p);
        p = fmaf(h1.x, v1.x, p); p = fmaf(h1.y, v1.y, p);
        p = fmaf(h1.z, v1.z, p); p = fmaf(h1.w, v1.w, p);
        p = fmaf(h2.x, v2.x, p); p = fmaf(h2.y, v2.y, p);
        p = fmaf(h2.z, v2.z, p); p = fmaf(h2.w, v2.w, p);
        p = fmaf(h3.x, v3.x, p); p = fmaf(h3.y, v3.y, p);
        p = fmaf(h3.z, v3.z, p); p = fmaf(h3.w, v3.w, p);
        if (addMode) p += sm->logit[b][n];       // final routing update: no store needed
        else         sm->logit[b][n] = p;
        const float e = __expf(p);               // softmax shift-invariant: no max needed,
        sm->cbuf[b][n] = e;                      // |logit| <= 2*max||uh_row|| << 88
        if (b) z1 += e; else z0 += e;
    }
    #pragma unroll
    for (int sft = 16; sft >= 1; sft >>= 1) {
        z0 += __shfl_xor_sync(0xffffffffu, z0, sft);
        z1 += __shfl_xor_sync(0xffffffffu, z1, sft);
    }
    if (lane == 0) { sm->zred[w][0] = z0; sm->zred[w][1] = z1; }
    __syncthreads();
}

__global__ __launch_bounds__(NTHREADS, 1)
void caps_routing_kernel(const float* __restrict__ u, const float* __restrict__ W,
                         float* __restrict__ out) {
    extern __shared__ char smem_bytes[];
    SmemLayout* sm = reinterpret_cast<SmemLayout*>(smem_bytes);

    const int k  = blockIdx.y;
    const int b0 = blockIdx.x * BTILE;
    const int t  = threadIdx.x;
    const int lane = t & 31, w = t >> 5;

    // ---- Phase 1: u_hat into padded SMEM; fuse the iteration-0 (uniform-c) s-sum ----
    {
        const int oq = t & 3;                 // which float4 of the 16-wide output row
        const int r  = t >> 2;                // 0..127
        const float* Wk  = W + (size_t)k * NC * ICC * OC;
        const float* ub0 = u + (size_t)b0 * NC * ICC;
        const float* ub1 = ub0 + (size_t)NC * ICC;
        float4 s0 = make_float4(0.f,0.f,0.f,0.f), s1 = make_float4(0.f,0.f,0.f,0.f);
        for (int n = r; n < NC; n += 128) {
            const float4 a0 = *(const float4*)(ub0 + (size_t)n * ICC);
            const float4 a1 = *(const float4*)(ub0 + (size_t)n * ICC + 4);
            const float4 c0 = *(const float4*)(ub1 + (size_t)n * ICC);
            const float4 c1 = *(const float4*)(ub1 + (size_t)n * ICC + 4);
            const float u0[8] = {a0.x, a0.y, a0.z, a0.w, a1.x, a1.y, a1.z, a1.w};
            const float u1[8] = {c0.x, c0.y, c0.z, c0.w, c1.x, c1.y, c1.z, c1.w};
            float4 acc0 = make_float4(0.f,0.f,0.f,0.f);
            float4 acc1 = make_float4(0.f,0.f,0.f,0.f);
            const float* wp = Wk + (size_t)n * ICC * OC + oq * 4;
            #pragma unroll
            for (int i = 0; i < ICC; i++) {
                const float4 wv = *(const float4*)(wp + i * OC);
                acc0.x = fmaf(wv.x, u0[i], acc0.x); acc0.y = fmaf(wv.y, u0[i], acc0.y);
                acc0.z = fmaf(wv.z, u0[i], acc0.z); acc0.w = fmaf(wv.w, u0[i], acc0.w);
                acc1.x = fmaf(wv.x, u1[i], acc1.x); acc1.y = fmaf(wv.y, u1[i], acc1.y);
                acc1.z = fmaf(wv.z, u1[i], acc1.z); acc1.w = fmaf(wv.w, u1[i], acc1.w);
            }
            *(float4*)&sm->uh[0][n][oq * 4] = acc0;
            *(float4*)&sm->uh[1][n][oq * 4] = acc1;
            s0.x += acc0.x; s0.y += acc0.y; s0.z += acc0.z; s0.w += acc0.w;
            s1.x += acc1.x; s1.y += acc1.y; s1.z += acc1.z; s1.w += acc1.w;
        }
        // reduce over the 8 lanes sharing this oq (lanes differ in bits 2..4)
        #pragma unroll
        for (int sft = 4; sft <= 16; sft <<= 1) {
            s0.x += __shfl_xor_sync(0xffffffffu, s0.x, sft);
            s0.y += __shfl_xor_sync(0xffffffffu, s0.y, sft);
            s0.z += __shfl_xor_sync(0xffffffffu, s0.z, sft);
            s0.w += __shfl_xor_sync(0xffffffffu, s0.w, sft);
            s1.x += __shfl_xor_sync(0xffffffffu, s1.x, sft);
            s1.y += __shfl_xor_sync(0xffffffffu, s1.y, sft);
            s1.z += __shfl_xor_sync(0xffffffffu, s1.z, sft);
            s1.w += __shfl_xor_sync(0xffffffffu, s1.w, sft);
        }
        if (lane < 4) { sm->sredA[w][lane][0] = s0; sm->sredA[w][lane][1] = s1; }
    }
    __syncthreads();

    // ---- Iteration 0: b=0 => c exactly uniform; s already summed in phase 1 ----
    squash_stage(sm, t, /*mode=*/0, /*writeOut=*/false, out, k, b0);
    pass_a_exp(sm, t, /*addMode=*/false);

    // ---- Iteration 1 ----
    pass_s_weighted(sm, t);
    squash_stage(sm, t, /*mode=*/1, /*writeOut=*/false, out, k, b0);
    pass_a_exp(sm, t, /*addMode=*/true);

    // ---- Iteration 2 (final) ----
    pass_s_weighted(sm, t);
    squash_stage(sm, t, /*mode=*/1, /*writeOut=*/true, out, k, b0);
}

extern "C" void kernel_launch(void* const* d_in, const int* in_sizes, int n_in,
                              void* d_out, int out_size) {
    const float* u = (const float*)d_in[0];   // [256, 1152, 8]
    const float* W = (const float*)d_in[1];   // [10, 1152, 8, 16]
    float* out = (float*)d_out;               // [10, 256, 1, 1, 16]

    cudaFuncSetAttribute(caps_routing_kernel,
                         cudaFuncAttributeMaxDynamicSharedMemorySize,
                         (int)sizeof(SmemLayout));
    dim3 grid(BT / BTILE, KC);                // 128 x 10 = 1280 CTAs
    caps_routing_kernel<<<grid, NTHREADS, sizeof(SmemLayout)>>>(u, W, out);
}

// round 5
// speedup vs baseline: 1.7988x; 1.2160x over previous
#include <cuda_runtime.h>
#include <math.h>

#define KC       10
#define BT       256
#define NC       1152
#define ICC      8
#define OC       16
#define BTILE    2
#define NTHREADS 576
#define NWARP    18
#define WPB      9        // warps per batch element (routing)
#define RPB      288      // routing threads per batch element
#define P1R      144      // phase-1 row stride (576/4)
#define PAD      20       // uh row stride: (20n mod 32) distinct over 8 lanes -> conflict-free LDS.128

struct SmemLayout {
    float  uh[BTILE][NC][PAD];        // 184320 B
    float4 sredA[NWARP][4][BTILE];    // phase-1 fused s0 partials
    float  sredB[NWARP][OC];          // fused-pass s partials (component-indexed)
    float  zred[NWARP];               // per-warp Z partial (warp is b-homogeneous)
    float4 v4[BTILE][4];              // v_j
};

// Reduce a 16-float vector across the 32 lanes of a warp with 16 SHFLs.
// On return, lane l holds the fully reduced component c(l) = bitrev4(l & 15)
// (duplicated in lanes l and l^16).
__device__ __forceinline__ float reduce16(const float a[16], int lane) {
    const bool b0 = lane & 1, b1 = lane & 2, b2 = lane & 4, b3 = lane & 8;
    float t8[8], t4[4], t2[2], r;
    #pragma unroll
    for (int j = 0; j < 8; j++) {
        const float send = b0 ? a[j]     : a[8 + j];
        const float keep = b0 ? a[8 + j] : a[j];
        t8[j] = keep + __shfl_xor_sync(0xffffffffu, send, 1);
    }
    #pragma unroll
    for (int j = 0; j < 4; j++) {
        const float send = b1 ? t8[j]     : t8[4 + j];
        const float keep = b1 ? t8[4 + j] : t8[j];
        t4[j] = keep + __shfl_xor_sync(0xffffffffu, send, 2);
    }
    #pragma unroll
    for (int j = 0; j < 2; j++) {
        const float send = b2 ? t4[j]     : t4[2 + j];
        const float keep = b2 ? t4[2 + j] : t4[j];
        t2[j] = keep + __shfl_xor_sync(0xffffffffu, send, 4);
    }
    {
        const float send = b3 ? t2[0] : t2[1];
        const float keep = b3 ? t2[1] : t2[0];
        r = keep + __shfl_xor_sync(0xffffffffu, send, 8);
    }
    r += __shfl_xor_sync(0xffffffffu, r, 16);
    return r;
}

// Final 32-thread stage: combine per-warp partials, normalize by Z, squash -> v4.
__device__ __forceinline__ void squash_stage(SmemLayout* sm, int t, int mode,
                                             bool writeOut, float* out, int k, int b0) {
    if (t < 32) {
        const int b = t >> 4, o = t & 15;
        float s = 0.f, Z;
        if (mode == 0) {                 // uniform-c iteration 0 (partials in sredA)
            const int og = o >> 2, oc = o & 3;
            #pragma unroll
            for (int w = 0; w < NWARP; w++)
                s += ((const float*)&sm->sredA[w][og][b])[oc];
            Z = (float)NC;
        } else {                         // weighted (partials in sredB / zred)
            #pragma unroll
            for (int w = 0; w < WPB; w++) s += sm->sredB[b * WPB + w][o];
            Z = 0.f;
            #pragma unroll
            for (int w = 0; w < WPB; w++) Z += sm->zred[b * WPB + w];
        }
        s /= Z;
        float sq = s * s;
        #pragma unroll
        for (int sft = 1; sft < 16; sft <<= 1)     // reduce within the 16-lane b-group
            sq += __shfl_xor_sync(0xffffffffu, sq, sft);
        const float v = s * sqrtf(sq) / (1.0f + sq);   // squash
        ((float*)&sm->v4[b])[o] = v;
        if (writeOut) out[((size_t)k * BT + b0 + b) * OC + o] = v;
    }
    __syncthreads();
}

// Fused routing pass: logit update + exp + Z + c-weighted s partial, ONE read of uh.
// Thread owns rows n = r + j*RPB (j=0..3) of batch element b; logit[] persists in regs.
__device__ __forceinline__ void routing_pass(SmemLayout* sm, int b, int r, int lane, int w,
                                             float logit[4], bool addMode) {
    const float4 v0 = sm->v4[b][0], v1 = sm->v4[b][1];
    const float4 v2 = sm->v4[b][2], v3 = sm->v4[b][3];
    float sacc[16];
    #pragma unroll
    for (int o = 0; o < 16; o++) sacc[o] = 0.f;
    float z = 0.f;
    #pragma unroll
    for (int j = 0; j < 4; j++) {
        const int n = r + j * RPB;
        const float4* hp = (const float4*)&sm->uh[b][n][0];
        const float4 h0 = hp[0], h1 = hp[1], h2 = hp[2], h3 = hp[3];
        float p = h0.x * v0.x;
        p = fmaf(h0.y, v0.y, p); p = fmaf(h0.z, v0.z, p); p = fmaf(h0.w, v0.w, p);
        p = fmaf(h1.x, v1.x, p); p = fmaf(h1.y, v1.y, p);
        p = fmaf(h1.z, v1.z, p); p = fmaf(h1.w, v1.w, p);
        p = fmaf(h2.x, v2.x, p); p = fmaf(h2.y, v2.y, p);
        p = fmaf(h2.z, v2.z, p); p = fmaf(h2.w, v2.w, p);
        p = fmaf(h3.x, v3.x, p); p = fmaf(h3.y, v3.y, p);
        p = fmaf(h3.z, v3.z, p); p = fmaf(h3.w, v3.w, p);
        if (addMode) p += logit[j];
        logit[j] = p;
        const float c = __expf(p);     // softmax shift-invariant; |logit| << 88
        z += c;
        sacc[0]  = fmaf(c, h0.x, sacc[0]);  sacc[1]  = fmaf(c, h0.y, sacc[1]);
        sacc[2]  = fmaf(c, h0.z, sacc[2]);  sacc[3]  = fmaf(c, h0.w, sacc[3]);
        sacc[4]  = fmaf(c, h1.x, sacc[4]);  sacc[5]  = fmaf(c, h1.y, sacc[5]);
        sacc[6]  = fmaf(c, h1.z, sacc[6]);  sacc[7]  = fmaf(c, h1.w, sacc[7]);
        sacc[8]  = fmaf(c, h2.x, sacc[8]);  sacc[9]  = fmaf(c, h2.y, sacc[9]);
        sacc[10] = fmaf(c, h2.z, sacc[10]); sacc[11] = fmaf(c, h2.w, sacc[11]);
        sacc[12] = fmaf(c, h3.x, sacc[12]); sacc[13] = fmaf(c, h3.y, sacc[13]);
        sacc[14] = fmaf(c, h3.z, sacc[14]); sacc[15] = fmaf(c, h3.w, sacc[15]);
    }
    const float sv = reduce16(sacc, lane);
    #pragma unroll
    for (int sft = 1; sft <= 16; sft <<= 1)
        z += __shfl_xor_sync(0xffffffffu, z, sft);
    if (lane == 0) sm->zred[w] = z;
    if (!(lane & 16)) {
        const int c = ((lane & 1) << 3) | ((lane & 2) << 1) | ((lane & 4) >> 1) | ((lane & 8) >> 3);
        sm->sredB[w][c] = sv;
    }
    __syncthreads();
}

__global__ __launch_bounds__(NTHREADS, 1)
void caps_routing_kernel(const float* __restrict__ u, const float* __restrict__ W,
                         float* __restrict__ out) {
    extern __shared__ char smem_bytes[];
    SmemLayout* sm = reinterpret_cast<SmemLayout*>(smem_bytes);

    const int k  = blockIdx.y;
    const int b0 = blockIdx.x * BTILE;
    const int t  = threadIdx.x;
    const int lane = t & 31, w = t >> 5;

    // ---- Phase 1: u_hat -> SMEM, with the iteration-0 (uniform-c) s-sum fused ----
    {
        const int oq = t & 3;                 // which float4 of the 16-wide output row
        const int r  = t >> 2;                // 0..143
        const float* Wk  = W + (size_t)k * NC * ICC * OC;
        const float* ub0 = u + (size_t)b0 * NC * ICC;
        const float* ub1 = ub0 + (size_t)NC * ICC;
        float4 s0 = make_float4(0.f,0.f,0.f,0.f), s1 = make_float4(0.f,0.f,0.f,0.f);
        #pragma unroll
        for (int j = 0; j < NC / P1R; j++) {
            const int n = r + j * P1R;
            const float4 a0 = *(const float4*)(ub0 + (size_t)n * ICC);
            const float4 a1 = *(const float4*)(ub0 + (size_t)n * ICC + 4);
            const float4 c0 = *(const float4*)(ub1 + (size_t)n * ICC);
            const float4 c1 = *(const float4*)(ub1 + (size_t)n * ICC + 4);
            const float u0[8] = {a0.x, a0.y, a0.z, a0.w, a1.x, a1.y, a1.z, a1.w};
            const float u1[8] = {c0.x, c0.y, c0.z, c0.w, c1.x, c1.y, c1.z, c1.w};
            float4 acc0 = make_float4(0.f,0.f,0.f,0.f);
            float4 acc1 = make_float4(0.f,0.f,0.f,0.f);
            const float* wp = Wk + (size_t)n * ICC * OC + oq * 4;
            #pragma unroll
            for (int i = 0; i < ICC; i++) {
                const float4 wv = *(const float4*)(wp + i * OC);
                acc0.x = fmaf(wv.x, u0[i], acc0.x); acc0.y = fmaf(wv.y, u0[i], acc0.y);
                acc0.z = fmaf(wv.z, u0[i], acc0.z); acc0.w = fmaf(wv.w, u0[i], acc0.w);
                acc1.x = fmaf(wv.x, u1[i], acc1.x); acc1.y = fmaf(wv.y, u1[i], acc1.y);
                acc1.z = fmaf(wv.z, u1[i], acc1.z); acc1.w = fmaf(wv.w, u1[i], acc1.w);
            }
            *(float4*)&sm->uh[0][n][oq * 4] = acc0;
            *(float4*)&sm->uh[1][n][oq * 4] = acc1;
            s0.x += acc0.x; s0.y += acc0.y; s0.z += acc0.z; s0.w += acc0.w;
            s1.x += acc1.x; s1.y += acc1.y; s1.z += acc1.z; s1.w += acc1.w;
        }
        // reduce over the 8 lanes sharing this oq (lane bits 2..4)
        #pragma unroll
        for (int sft = 4; sft <= 16; sft <<= 1) {
            s0.x += __shfl_xor_sync(0xffffffffu, s0.x, sft);
            s0.y += __shfl_xor_sync(0xffffffffu, s0.y, sft);
            s0.z += __shfl_xor_sync(0xffffffffu, s0.z, sft);
            s0.w += __shfl_xor_sync(0xffffffffu, s0.w, sft);
            s1.x += __shfl_xor_sync(0xffffffffu, s1.x, sft);
            s1.y += __shfl_xor_sync(0xffffffffu, s1.y, sft);
            s1.z += __shfl_xor_sync(0xffffffffu, s1.z, sft);
            s1.w += __shfl_xor_sync(0xffffffffu, s1.w, sft);
        }
        if (lane < 4) { sm->sredA[w][lane][0] = s0; sm->sredA[w][lane][1] = s1; }
    }
    __syncthreads();

    // ---- Iteration 0: b_ij = 0 => c exactly uniform; s already summed in phase 1 ----
    squash_stage(sm, t, /*mode=*/0, /*writeOut=*/false, out, k, b0);

    // ---- Routing thread mapping: 288 threads per batch element, 4 rows each ----
    const int rb = (t >= RPB) ? 1 : 0;
    const int rr = t - rb * RPB;
    float logit[4];

    // ---- Iteration 1 (fused a+exp+s) ----
    routing_pass(sm, rb, rr, lane, w, logit, /*addMode=*/false);
    squash_stage(sm, t, /*mode=*/1, /*writeOut=*/false, out, k, b0);

    // ---- Iteration 2 (final) ----
    routing_pass(sm, rb, rr, lane, w, logit, /*addMode=*/true);
    squash_stage(sm, t, /*mode=*/1, /*writeOut=*/true, out, k, b0);
}

extern "C" void kernel_launch(void* const* d_in, const int* in_sizes, int n_in,
                              void* d_out, int out_size) {
    const float* u = (const float*)d_in[0];   // [256, 1152, 8]
    const float* W = (const float*)d_in[1];   // [10, 1152, 8, 16]
    float* out = (float*)d_out;               // [10, 256, 1, 1, 16]

    cudaFuncSetAttribute(caps_routing_kernel,
                         cudaFuncAttributeMaxDynamicSharedMemorySize,
                         (int)sizeof(SmemLayout));
    dim3 grid(BT / BTILE, KC);                // 128 x 10 = 1280 CTAs
    caps_routing_kernel<<<grid, NTHREADS, sizeof(SmemLayout)>>>(u, W, out);
}